// round 10
// baseline (speedup 1.0000x reference)
#include <cuda_runtime.h>
#include <cuda_fp16.h>
#include <cstdint>

#define N_NODES 64000
#define N_GRAPHS 128
#define D 64
#define SRC_CAP 128   // padded adjacency capacity (Poisson(16) max deg ~45)

// ---------------- scratch (device globals; zero-initialized at load) -------
// INVARIANT: g_deg, g_pool, g_gcnt, g_done are zero at entry of every run;
// the last kernels of each run restore them after last use.
__device__ __half g_xh[N_NODES * D];       // fp16 feature tables
__device__ __half g_hh0[N_NODES * D];
__device__ __half g_hh1[N_NODES * D];
__device__ __half g_aggr_h[N_NODES * D];   // fp16 aggregated features
__device__ __half g_wh[3 * 128 * 64];      // concat [Wl^T ; Wr^T] per layer, k-major
__device__ float  g_y[N_NODES * 2];
__device__ int    g_deg[N_NODES];          // degree AND bucket-fill counter
__device__ int    g_srcs[N_NODES * SRC_CAP];
__device__ float  g_pool[N_GRAPHS * 2];
__device__ int    g_gcnt[N_GRAPHS];
__device__ int    g_is64;
__device__ int    g_done;

__device__ __forceinline__ const __half2* sel_h(int s) {
    return (const __half2*)(s == 0 ? g_xh : (s == 1 ? g_hh0 : g_hh1));
}
__device__ __forceinline__ int load_idx(const void* p, int i) {
    return g_is64 ? (int)((const long long*)p)[i] : ((const int*)p)[i];
}
__device__ __forceinline__ uint32_t smem_u32(const void* p) {
    return (uint32_t)__cvta_generic_to_shared(p);
}
__device__ __forceinline__ int probe64(const void* edges) {
    const long long* p = (const long long*)edges;
    int ok = 1;
    #pragma unroll
    for (int q = 0; q < 16; q++) {
        long long v = p[q];
        if (v < 0 || v >= N_NODES) ok = 0;
    }
    return ok;
}

// ---- K1: fused prologue: tohalf + wconv + direct bucket fill + gcnt ------
__global__ void k_pro(const void* edges, const float* __restrict__ x,
                      const float* __restrict__ Wl, const float* __restrict__ Wr,
                      const void* __restrict__ batch, int E) {
    __shared__ int s_is64;
    __shared__ int h[N_GRAPHS];
    const int do_hist = (blockIdx.x < (N_NODES + 255) / 256);
    if (threadIdx.x == 0) s_is64 = probe64(edges);
    if (do_hist && threadIdx.x < N_GRAPHS) h[threadIdx.x] = 0;
    __syncthreads();
    int is64 = s_is64;
    int i = blockIdx.x * blockDim.x + threadIdx.x;
    if (i == 0) g_is64 = is64;
    if (i < N_NODES * D / 4) {
        float4 v = ((const float4*)x)[i];
        __half2* o = (__half2*)g_xh;
        o[i * 2]     = __floats2half2_rn(v.x, v.y);
        o[i * 2 + 1] = __floats2half2_rn(v.z, v.w);
    }
    if (i < 3 * 128 * 64) {
        int l = i >> 13;
        int r = i & 8191;
        int k = r >> 6, j = r & 63;
        float v = (k < 64) ? Wl[l * 4096 + j * 64 + k] : Wr[l * 4096 + j * 64 + (k - 64)];
        g_wh[i] = __float2half_rn(v);
    }
    int e = i * 2;
    if (e < E) {
        int s0, s1, d0, d1;
        if (is64) {
            longlong2 s = *(const longlong2*)((const long long*)edges + e);
            longlong2 d = *(const longlong2*)((const long long*)edges + E + e);
            s0 = (int)s.x; s1 = (int)s.y; d0 = (int)d.x; d1 = (int)d.y;
        } else {
            int2 s = *(const int2*)((const int*)edges + e);
            int2 d = *(const int2*)((const int*)edges + E + e);
            s0 = s.x; s1 = s.y; d0 = d.x; d1 = d.y;
        }
        int p0 = atomicAdd(&g_deg[d0], 1);
        if (p0 < SRC_CAP) g_srcs[d0 * SRC_CAP + p0] = s0;
        if (e + 1 < E) {
            int p1 = atomicAdd(&g_deg[d1], 1);
            if (p1 < SRC_CAP) g_srcs[d1 * SRC_CAP + p1] = s1;
        }
    }
    if (do_hist) {
        if (i < N_NODES) {
            int gidx = is64 ? (int)((const long long*)batch)[i] : ((const int*)batch)[i];
            atomicAdd(&h[gidx], 1);
        }
        __syncthreads();
        if (threadIdx.x < N_GRAPHS && h[threadIdx.x])
            atomicAdd(&g_gcnt[threadIdx.x], h[threadIdx.x]);
    }
}

// ---------------- mean aggregation: warp per node, uint4 lanes ------------
// Issue-bound fix: 2-level HADD2 tree over 4 edges BEFORE converting to
// fp32 -> 28 arith ops per 16-edge group per lane instead of 64.
__device__ __forceinline__ void add8(float* acc, uint4 v) {
    float2 a = __half22float2(*(__half2*)&v.x);
    float2 b = __half22float2(*(__half2*)&v.y);
    float2 c = __half22float2(*(__half2*)&v.z);
    float2 d = __half22float2(*(__half2*)&v.w);
    acc[0] += a.x; acc[1] += a.y; acc[2] += b.x; acc[3] += b.y;
    acc[4] += c.x; acc[5] += c.y; acc[6] += d.x; acc[7] += d.y;
}

__global__ void k_aggregate(int in_sel) {
    const __half* __restrict__ in = (const __half*)sel_h(in_sel);
    int warp = (blockIdx.x * blockDim.x + threadIdx.x) >> 5;
    int lane = threadIdx.x & 31;
    if (warp >= N_NODES) return;
    int g = lane >> 3, r = lane & 7;
    int deg = g_deg[warp];
    int de = min(deg, SRC_CAP);
    const int* sp = g_srcs + warp * SRC_CAP;
    float acc[8] = {0.f, 0.f, 0.f, 0.f, 0.f, 0.f, 0.f, 0.f};
    int e = 0;
    for (; e + 16 <= de; e += 16) {
        int s0 = sp[e + g];
        int s1 = sp[e + 4 + g];
        int s2 = sp[e + 8 + g];
        int s3 = sp[e + 12 + g];
        uint4 v0 = *(const uint4*)(in + s0 * 64 + r * 8);
        uint4 v1 = *(const uint4*)(in + s1 * 64 + r * 8);
        uint4 v2 = *(const uint4*)(in + s2 * 64 + r * 8);
        uint4 v3 = *(const uint4*)(in + s3 * 64 + r * 8);
        const __half2* p0 = (const __half2*)&v0;
        const __half2* p1 = (const __half2*)&v1;
        const __half2* p2 = (const __half2*)&v2;
        const __half2* p3 = (const __half2*)&v3;
        #pragma unroll
        for (int j = 0; j < 4; j++) {
            __half2 a = __hadd2(p0[j], p1[j]);
            __half2 b = __hadd2(p2[j], p3[j]);
            float2 f = __half22float2(__hadd2(a, b));
            acc[2 * j]     += f.x;
            acc[2 * j + 1] += f.y;
        }
    }
    for (; e < de; e += 4) {
        if (e + g < de) {
            int s = sp[e + g];
            uint4 v = *(const uint4*)(in + s * 64 + r * 8);
            add8(acc, v);
        }
    }
    #pragma unroll
    for (int i = 0; i < 8; i++) {
        acc[i] += __shfl_xor_sync(0xFFFFFFFFu, acc[i], 8);
        acc[i] += __shfl_xor_sync(0xFFFFFFFFu, acc[i], 16);
    }
    if (g == 0) {
        float iv = deg > 0 ? 1.0f / (float)deg : 0.f;
        uint4 o;
        *(__half2*)&o.x = __floats2half2_rn(acc[0] * iv, acc[1] * iv);
        *(__half2*)&o.y = __floats2half2_rn(acc[2] * iv, acc[3] * iv);
        *(__half2*)&o.z = __floats2half2_rn(acc[4] * iv, acc[5] * iv);
        *(__half2*)&o.w = __floats2half2_rn(acc[6] * iv, acc[7] * iv);
        *(uint4*)(g_aggr_h + warp * 64 + r * 8) = o;
    }
}

// ---------------- HMMA dual GEMM + bias + relu (+ fused projection) -------
#define LWS_A 136
#define LWS_W 72
__global__ void __launch_bounds__(256)
k_linear_hmma(int in_sel, int out_sel, int layer, const float* __restrict__ bias,
              int do_proj, const float* __restrict__ WlO,
              const float* __restrict__ WrO, const void* __restrict__ batch) {
    __shared__ __half wS[128 * LWS_W];
    __shared__ __half sA[32 * LWS_A];
    __shared__ float sYp[8][32][4];
    __shared__ float pb[N_GRAPHS * 2];
    const __half* in = (const __half*)sel_h(in_sel);
    __half2* out = (__half2*)(out_sel == 1 ? g_hh0 : g_hh1);
    int t = threadIdx.x;
    int lane = t & 31;
    int w = t >> 5;

    {
        const __half2* src = (const __half2*)(g_wh + layer * 8192);
        for (int i = t; i < 4096; i += 256) {
            int k = i >> 5, jp = i & 31;
            *(__half2*)&wS[k * LWS_W + jp * 2] = src[i];
        }
        if (do_proj && t < N_GRAPHS * 2) pb[t] = 0.f;
    }
    __syncthreads();

    uint32_t B[8][2];
    #pragma unroll
    for (int ks = 0; ks < 8; ks++) {
        uint32_t addr = smem_u32(&wS[(ks * 16 + (lane & 15)) * LWS_W + w * 8]);
        asm volatile("ldmatrix.sync.aligned.m8n8.x2.trans.shared.b16 {%0,%1}, [%2];\n"
                     : "=r"(B[ks][0]), "=r"(B[ks][1]) : "r"(addr));
    }

    float2 b2 = *(const float2*)&bias[w * 8 + 2 * (lane & 3)];
    int c = w * 8 + 2 * (lane & 3);
    float wl0a = 0, wl0b = 0, wl1a = 0, wl1b = 0, wr0a = 0, wr0b = 0, wr1a = 0, wr1b = 0;
    if (do_proj) {
        wl0a = WlO[c];      wl0b = WlO[c + 1];
        wl1a = WlO[64 + c]; wl1b = WlO[64 + c + 1];
        wr0a = WrO[c];      wr0b = WrO[c + 1];
        wr1a = WrO[64 + c]; wr1b = WrO[64 + c + 1];
    }

    const int ntiles = N_NODES / 32;
    for (int tile = blockIdx.x; tile < ntiles; tile += gridDim.x) {
        int base = tile * 32;
        for (int cc = t; cc < 512; cc += 256) {
            int row = cc >> 4, c16 = cc & 15;
            const __half* srcp = (c16 < 8)
                ? (g_aggr_h + (base + row) * 64 + c16 * 8)
                : (in       + (base + row) * 64 + (c16 - 8) * 8);
            *(uint4*)&sA[row * LWS_A + c16 * 8] = *(const uint4*)srcp;
        }
        __syncthreads();

        #pragma unroll
        for (int mt = 0; mt < 2; mt++) {
            float acc[4] = {b2.x, b2.y, b2.x, b2.y};
            #pragma unroll
            for (int ks = 0; ks < 8; ks++) {
                uint32_t a0, a1, a2, a3;
                uint32_t addr = smem_u32(&sA[(mt * 16 + (lane & 15)) * LWS_A
                                             + ks * 16 + (lane >> 4) * 8]);
                asm volatile("ldmatrix.sync.aligned.m8n8.x4.shared.b16 {%0,%1,%2,%3}, [%4];\n"
                             : "=r"(a0), "=r"(a1), "=r"(a2), "=r"(a3) : "r"(addr));
                asm volatile("mma.sync.aligned.m16n8k16.row.col.f32.f16.f16.f32 "
                             "{%0,%1,%2,%3}, {%4,%5,%6,%7}, {%8,%9}, {%0,%1,%2,%3};\n"
                             : "+f"(acc[0]), "+f"(acc[1]), "+f"(acc[2]), "+f"(acc[3])
                             : "r"(a0), "r"(a1), "r"(a2), "r"(a3),
                               "r"(B[ks][0]), "r"(B[ks][1]));
            }
            float x0 = fmaxf(acc[0], 0.f), x1 = fmaxf(acc[1], 0.f);
            float x2 = fmaxf(acc[2], 0.f), x3 = fmaxf(acc[3], 0.f);
            int row0 = base + mt * 16 + (lane >> 2);
            int colp = w * 4 + (lane & 3);
            out[row0 * 32 + colp] = __floats2half2_rn(x0, x1);
            out[(row0 + 8) * 32 + colp] = __floats2half2_rn(x2, x3);
            if (do_proj) {
                float p0 = x0 * wl0a + x1 * wl0b, p1 = x0 * wl1a + x1 * wl1b;
                float p2 = x0 * wr0a + x1 * wr0b, p3 = x0 * wr1a + x1 * wr1b;
                float q0 = x2 * wl0a + x3 * wl0b, q1 = x2 * wl1a + x3 * wl1b;
                float q2 = x2 * wr0a + x3 * wr0b, q3 = x2 * wr1a + x3 * wr1b;
                #pragma unroll
                for (int s = 1; s <= 2; s <<= 1) {
                    p0 += __shfl_xor_sync(0xFFFFFFFFu, p0, s);
                    p1 += __shfl_xor_sync(0xFFFFFFFFu, p1, s);
                    p2 += __shfl_xor_sync(0xFFFFFFFFu, p2, s);
                    p3 += __shfl_xor_sync(0xFFFFFFFFu, p3, s);
                    q0 += __shfl_xor_sync(0xFFFFFFFFu, q0, s);
                    q1 += __shfl_xor_sync(0xFFFFFFFFu, q1, s);
                    q2 += __shfl_xor_sync(0xFFFFFFFFu, q2, s);
                    q3 += __shfl_xor_sync(0xFFFFFFFFu, q3, s);
                }
                if ((lane & 3) == 0) {
                    int rr = mt * 16 + (lane >> 2);
                    sYp[w][rr][0] = p0; sYp[w][rr][1] = p1;
                    sYp[w][rr][2] = p2; sYp[w][rr][3] = p3;
                    sYp[w][rr + 8][0] = q0; sYp[w][rr + 8][1] = q1;
                    sYp[w][rr + 8][2] = q2; sYp[w][rr + 8][3] = q3;
                }
            }
        }
        __syncthreads();
        if (do_proj && t < 128) {
            int row = t >> 2, o = t & 3;
            float s = sYp[0][row][o] + sYp[1][row][o] + sYp[2][row][o] + sYp[3][row][o]
                    + sYp[4][row][o] + sYp[5][row][o] + sYp[6][row][o] + sYp[7][row][o];
            int node = base + row;
            if (o < 2) {
                g_y[node * 2 + o] = s;
            } else {
                int gb = load_idx(batch, node);
                atomicAdd(&pb[gb * 2 + (o - 2)], s);
            }
        }
    }
    if (do_proj) {
        __syncthreads();
        if (t < N_GRAPHS * 2 && pb[t] != 0.f) atomicAdd(&g_pool[t], pb[t]);
    }
}

// ---- K8: gather 2-dim y over edges + pool + last-block output + cleanup --
__global__ void k_gather2(const void* __restrict__ batch,
                          const float* __restrict__ b_out,
                          float* __restrict__ out) {
    __shared__ float sp[N_GRAPHS * 2];
    __shared__ int s_last;
    for (int i = threadIdx.x; i < N_GRAPHS * 2; i += blockDim.x) sp[i] = 0.f;
    __syncthreads();
    int n = blockIdx.x * blockDim.x + threadIdx.x;
    if (n < N_NODES) {
        int deg = g_deg[n];
        int de = min(deg, SRC_CAP);
        g_deg[n] = 0;   // restore zero-invariant (last reader)
        const int* spn = g_srcs + n * SRC_CAP;
        const float2* y2 = (const float2*)g_y;
        float a0 = 0.f, a1 = 0.f, b0 = 0.f, b1 = 0.f;
        int e = 0;
        for (; e + 4 <= de; e += 4) {
            float2 v0 = y2[spn[e]];
            float2 v1 = y2[spn[e + 1]];
            float2 v2 = y2[spn[e + 2]];
            float2 v3 = y2[spn[e + 3]];
            a0 += v0.x + v1.x; b0 += v2.x + v3.x;
            a1 += v0.y + v1.y; b1 += v2.y + v3.y;
        }
        for (; e < de; e++) {
            float2 v = y2[spn[e]];
            a0 += v.x; a1 += v.y;
        }
        float iv = deg > 0 ? 1.0f / (float)deg : 0.f;
        int g = load_idx(batch, n);
        atomicAdd(&sp[g * 2 + 0], (a0 + b0) * iv);
        atomicAdd(&sp[g * 2 + 1], (a1 + b1) * iv);
    }
    __syncthreads();
    for (int i = threadIdx.x; i < N_GRAPHS * 2; i += blockDim.x)
        if (sp[i] != 0.f) atomicAdd(&g_pool[i], sp[i]);

    __threadfence();
    __syncthreads();
    if (threadIdx.x == 0)
        s_last = (atomicAdd(&g_done, 1) == (int)gridDim.x - 1) ? 1 : 0;
    __syncthreads();
    if (s_last) {
        int i = threadIdx.x;
        float p = 0.f; int cnum = 0;
        if (i < N_GRAPHS * 2) {
            cnum = g_gcnt[i >> 1];
            p = g_pool[i];
            out[i] = (cnum > 0 ? p / (float)cnum : 0.f) + b_out[i & 1];
        }
        __syncthreads();
        if (i < N_GRAPHS * 2) {
            g_pool[i] = 0.f;
            if ((i & 1) == 0) g_gcnt[i >> 1] = 0;
        }
        if (i == 0) g_done = 0;
    }
}

// ---------------- launch ---------------------------------------------------
extern "C" void kernel_launch(void* const* d_in, const int* in_sizes, int n_in,
                              void* d_out, int out_size) {
    const float* x      = (const float*)d_in[0];
    const void*  edges  = d_in[1];
    const void*  batch  = d_in[2];
    const float* Wl     = (const float*)d_in[3];
    const float* Wr     = (const float*)d_in[4];
    const float* b      = (const float*)d_in[5];
    const float* Wl_out = (const float*)d_in[6];
    const float* Wr_out = (const float*)d_in[7];
    const float* b_out  = (const float*)d_in[8];
    float* out = (float*)d_out;
    int E = in_sizes[1] / 2;

    k_pro<<<(N_NODES * D / 4 + 255) / 256, 256>>>(edges, x, Wl, Wr, batch, E);

    k_aggregate<<<N_NODES / 8, 256>>>(0);
    k_linear_hmma<<<500, 256>>>(0, 1, 0, b, 0, Wl_out, Wr_out, batch);
    k_aggregate<<<N_NODES / 8, 256>>>(1);
    k_linear_hmma<<<500, 256>>>(1, 2, 1, b + 64, 0, Wl_out, Wr_out, batch);
    k_aggregate<<<N_NODES / 8, 256>>>(2);
    k_linear_hmma<<<500, 256>>>(2, 1, 2, b + 128, 1, Wl_out, Wr_out, batch);

    k_gather2<<<(N_NODES + 255) / 256, 256>>>(batch, b_out, out);
}

// round 11
// speedup vs baseline: 1.0627x; 1.0627x over previous
#include <cuda_runtime.h>
#include <cuda_fp16.h>
#include <cstdint>

#define N_NODES 64000
#define N_GRAPHS 128
#define D 64
#define SRC_CAP 128   // padded adjacency capacity (Poisson(16) max deg ~45)

// ---------------- scratch (device globals; zero-initialized at load) -------
// INVARIANT: g_deg, g_pool, g_gcnt, g_done are zero at entry of every run;
// the last kernels of each run restore them after last use.
__device__ __half g_xh[N_NODES * D];       // fp16 feature tables
__device__ __half g_hh0[N_NODES * D];
__device__ __half g_hh1[N_NODES * D];
__device__ __half g_aggr_h[N_NODES * D];   // fp16 aggregated features
__device__ __half g_wh[3 * 128 * 64];      // concat [Wl^T ; Wr^T] per layer, k-major
__device__ float  g_y[N_NODES * 2];
__device__ int    g_deg[N_NODES];          // degree AND bucket-fill counter
__device__ int    g_srcs[N_NODES * SRC_CAP];
__device__ float  g_pool[N_GRAPHS * 2];
__device__ int    g_gcnt[N_GRAPHS];
__device__ int    g_is64;
__device__ int    g_done;

__device__ __forceinline__ const __half2* sel_h(int s) {
    return (const __half2*)(s == 0 ? g_xh : (s == 1 ? g_hh0 : g_hh1));
}
__device__ __forceinline__ int load_idx(const void* p, int i) {
    return g_is64 ? (int)((const long long*)p)[i] : ((const int*)p)[i];
}
__device__ __forceinline__ uint32_t smem_u32(const void* p) {
    return (uint32_t)__cvta_generic_to_shared(p);
}
__device__ __forceinline__ int probe64(const void* edges) {
    const long long* p = (const long long*)edges;
    int ok = 1;
    #pragma unroll
    for (int q = 0; q < 16; q++) {
        long long v = p[q];
        if (v < 0 || v >= N_NODES) ok = 0;
    }
    return ok;
}

// ---- K1: fused prologue: tohalf + wconv + direct bucket fill + gcnt ------
__global__ void k_pro(const void* edges, const float* __restrict__ x,
                      const float* __restrict__ Wl, const float* __restrict__ Wr,
                      const void* __restrict__ batch, int E) {
    __shared__ int s_is64;
    __shared__ int h[N_GRAPHS];
    const int do_hist = (blockIdx.x < (N_NODES + 255) / 256);
    if (threadIdx.x == 0) s_is64 = probe64(edges);
    if (do_hist && threadIdx.x < N_GRAPHS) h[threadIdx.x] = 0;
    __syncthreads();
    int is64 = s_is64;
    int i = blockIdx.x * blockDim.x + threadIdx.x;
    if (i == 0) g_is64 = is64;
    if (i < N_NODES * D / 4) {
        float4 v = ((const float4*)x)[i];
        __half2* o = (__half2*)g_xh;
        o[i * 2]     = __floats2half2_rn(v.x, v.y);
        o[i * 2 + 1] = __floats2half2_rn(v.z, v.w);
    }
    if (i < 3 * 128 * 64) {
        int l = i >> 13;
        int r = i & 8191;
        int k = r >> 6, j = r & 63;
        float v = (k < 64) ? Wl[l * 4096 + j * 64 + k] : Wr[l * 4096 + j * 64 + (k - 64)];
        g_wh[i] = __float2half_rn(v);
    }
    int e = i * 2;
    if (e < E) {
        int s0, s1, d0, d1;
        if (is64) {
            longlong2 s = *(const longlong2*)((const long long*)edges + e);
            longlong2 d = *(const longlong2*)((const long long*)edges + E + e);
            s0 = (int)s.x; s1 = (int)s.y; d0 = (int)d.x; d1 = (int)d.y;
        } else {
            int2 s = *(const int2*)((const int*)edges + e);
            int2 d = *(const int2*)((const int*)edges + E + e);
            s0 = s.x; s1 = s.y; d0 = d.x; d1 = d.y;
        }
        int p0 = atomicAdd(&g_deg[d0], 1);
        if (p0 < SRC_CAP) g_srcs[d0 * SRC_CAP + p0] = s0;
        if (e + 1 < E) {
            int p1 = atomicAdd(&g_deg[d1], 1);
            if (p1 < SRC_CAP) g_srcs[d1 * SRC_CAP + p1] = s1;
        }
    }
    if (do_hist) {
        if (i < N_NODES) {
            int gidx = is64 ? (int)((const long long*)batch)[i] : ((const int*)batch)[i];
            atomicAdd(&h[gidx], 1);
        }
        __syncthreads();
        if (threadIdx.x < N_GRAPHS && h[threadIdx.x])
            atomicAdd(&g_gcnt[threadIdx.x], h[threadIdx.x]);
    }
}

// ---------------- mean aggregation: warp per node, uint4 lanes ------------
// Lane-group g owns 4 CONSECUTIVE edges (one int4 index load), HADD2 tree
// before fp32 accumulate, and __launch_bounds__(256,8) caps regs at 32 so
// occupancy stays at 100% (R10 lesson: 38 regs -> 59.9% occ -> regression).
__device__ __forceinline__ void add8(float* acc, uint4 v) {
    float2 a = __half22float2(*(__half2*)&v.x);
    float2 b = __half22float2(*(__half2*)&v.y);
    float2 c = __half22float2(*(__half2*)&v.z);
    float2 d = __half22float2(*(__half2*)&v.w);
    acc[0] += a.x; acc[1] += a.y; acc[2] += b.x; acc[3] += b.y;
    acc[4] += c.x; acc[5] += c.y; acc[6] += d.x; acc[7] += d.y;
}

__global__ void __launch_bounds__(256, 8) k_aggregate(int in_sel) {
    const __half* __restrict__ in = (const __half*)sel_h(in_sel);
    int warp = (blockIdx.x * blockDim.x + threadIdx.x) >> 5;
    int lane = threadIdx.x & 31;
    if (warp >= N_NODES) return;
    int g = lane >> 3, r = lane & 7;
    int deg = g_deg[warp];
    int de = min(deg, SRC_CAP);
    const int* sp = g_srcs + warp * SRC_CAP;
    float acc[8] = {0.f, 0.f, 0.f, 0.f, 0.f, 0.f, 0.f, 0.f};
    int e = 0;
    for (; e + 16 <= de; e += 16) {
        int4 s4 = *(const int4*)(sp + e + 4 * g);      // 4 consecutive edges
        uint4 v0 = *(const uint4*)(in + s4.x * 64 + r * 8);
        uint4 v1 = *(const uint4*)(in + s4.y * 64 + r * 8);
        uint4 v2 = *(const uint4*)(in + s4.z * 64 + r * 8);
        uint4 v3 = *(const uint4*)(in + s4.w * 64 + r * 8);
        const __half2* p0 = (const __half2*)&v0;
        const __half2* p1 = (const __half2*)&v1;
        const __half2* p2 = (const __half2*)&v2;
        const __half2* p3 = (const __half2*)&v3;
        #pragma unroll
        for (int j = 0; j < 4; j++) {
            __half2 a = __hadd2(p0[j], p1[j]);
            __half2 b = __hadd2(p2[j], p3[j]);
            float2 f = __half22float2(__hadd2(a, b));
            acc[2 * j]     += f.x;
            acc[2 * j + 1] += f.y;
        }
    }
    for (; e < de; e += 4) {
        if (e + g < de) {
            int s = sp[e + g];
            uint4 v = *(const uint4*)(in + s * 64 + r * 8);
            add8(acc, v);
        }
    }
    #pragma unroll
    for (int i = 0; i < 8; i++) {
        acc[i] += __shfl_xor_sync(0xFFFFFFFFu, acc[i], 8);
        acc[i] += __shfl_xor_sync(0xFFFFFFFFu, acc[i], 16);
    }
    if (g == 0) {
        float iv = deg > 0 ? 1.0f / (float)deg : 0.f;
        uint4 o;
        *(__half2*)&o.x = __floats2half2_rn(acc[0] * iv, acc[1] * iv);
        *(__half2*)&o.y = __floats2half2_rn(acc[2] * iv, acc[3] * iv);
        *(__half2*)&o.z = __floats2half2_rn(acc[4] * iv, acc[5] * iv);
        *(__half2*)&o.w = __floats2half2_rn(acc[6] * iv, acc[7] * iv);
        *(uint4*)(g_aggr_h + warp * 64 + r * 8) = o;
    }
}

// ---------------- HMMA dual GEMM + bias + relu (+ fused projection) -------
#define LWS_A 136
#define LWS_W 72
__global__ void __launch_bounds__(256)
k_linear_hmma(int in_sel, int out_sel, int layer, const float* __restrict__ bias,
              int do_proj, const float* __restrict__ WlO,
              const float* __restrict__ WrO, const void* __restrict__ batch) {
    __shared__ __half wS[128 * LWS_W];
    __shared__ __half sA[32 * LWS_A];
    __shared__ float sYp[8][32][4];
    __shared__ float pb[N_GRAPHS * 2];
    const __half* in = (const __half*)sel_h(in_sel);
    __half2* out = (__half2*)(out_sel == 1 ? g_hh0 : g_hh1);
    int t = threadIdx.x;
    int lane = t & 31;
    int w = t >> 5;

    {
        const __half2* src = (const __half2*)(g_wh + layer * 8192);
        for (int i = t; i < 4096; i += 256) {
            int k = i >> 5, jp = i & 31;
            *(__half2*)&wS[k * LWS_W + jp * 2] = src[i];
        }
        if (do_proj && t < N_GRAPHS * 2) pb[t] = 0.f;
    }
    __syncthreads();

    uint32_t B[8][2];
    #pragma unroll
    for (int ks = 0; ks < 8; ks++) {
        uint32_t addr = smem_u32(&wS[(ks * 16 + (lane & 15)) * LWS_W + w * 8]);
        asm volatile("ldmatrix.sync.aligned.m8n8.x2.trans.shared.b16 {%0,%1}, [%2];\n"
                     : "=r"(B[ks][0]), "=r"(B[ks][1]) : "r"(addr));
    }

    float2 b2 = *(const float2*)&bias[w * 8 + 2 * (lane & 3)];
    int c = w * 8 + 2 * (lane & 3);
    float wl0a = 0, wl0b = 0, wl1a = 0, wl1b = 0, wr0a = 0, wr0b = 0, wr1a = 0, wr1b = 0;
    if (do_proj) {
        wl0a = WlO[c];      wl0b = WlO[c + 1];
        wl1a = WlO[64 + c]; wl1b = WlO[64 + c + 1];
        wr0a = WrO[c];      wr0b = WrO[c + 1];
        wr1a = WrO[64 + c]; wr1b = WrO[64 + c + 1];
    }

    const int ntiles = N_NODES / 32;
    for (int tile = blockIdx.x; tile < ntiles; tile += gridDim.x) {
        int base = tile * 32;
        for (int cc = t; cc < 512; cc += 256) {
            int row = cc >> 4, c16 = cc & 15;
            const __half* srcp = (c16 < 8)
                ? (g_aggr_h + (base + row) * 64 + c16 * 8)
                : (in       + (base + row) * 64 + (c16 - 8) * 8);
            *(uint4*)&sA[row * LWS_A + c16 * 8] = *(const uint4*)srcp;
        }
        __syncthreads();

        #pragma unroll
        for (int mt = 0; mt < 2; mt++) {
            float acc[4] = {b2.x, b2.y, b2.x, b2.y};
            #pragma unroll
            for (int ks = 0; ks < 8; ks++) {
                uint32_t a0, a1, a2, a3;
                uint32_t addr = smem_u32(&sA[(mt * 16 + (lane & 15)) * LWS_A
                                             + ks * 16 + (lane >> 4) * 8]);
                asm volatile("ldmatrix.sync.aligned.m8n8.x4.shared.b16 {%0,%1,%2,%3}, [%4];\n"
                             : "=r"(a0), "=r"(a1), "=r"(a2), "=r"(a3) : "r"(addr));
                asm volatile("mma.sync.aligned.m16n8k16.row.col.f32.f16.f16.f32 "
                             "{%0,%1,%2,%3}, {%4,%5,%6,%7}, {%8,%9}, {%0,%1,%2,%3};\n"
                             : "+f"(acc[0]), "+f"(acc[1]), "+f"(acc[2]), "+f"(acc[3])
                             : "r"(a0), "r"(a1), "r"(a2), "r"(a3),
                               "r"(B[ks][0]), "r"(B[ks][1]));
            }
            float x0 = fmaxf(acc[0], 0.f), x1 = fmaxf(acc[1], 0.f);
            float x2 = fmaxf(acc[2], 0.f), x3 = fmaxf(acc[3], 0.f);
            int row0 = base + mt * 16 + (lane >> 2);
            int colp = w * 4 + (lane & 3);
            out[row0 * 32 + colp] = __floats2half2_rn(x0, x1);
            out[(row0 + 8) * 32 + colp] = __floats2half2_rn(x2, x3);
            if (do_proj) {
                float p0 = x0 * wl0a + x1 * wl0b, p1 = x0 * wl1a + x1 * wl1b;
                float p2 = x0 * wr0a + x1 * wr0b, p3 = x0 * wr1a + x1 * wr1b;
                float q0 = x2 * wl0a + x3 * wl0b, q1 = x2 * wl1a + x3 * wl1b;
                float q2 = x2 * wr0a + x3 * wr0b, q3 = x2 * wr1a + x3 * wr1b;
                #pragma unroll
                for (int s = 1; s <= 2; s <<= 1) {
                    p0 += __shfl_xor_sync(0xFFFFFFFFu, p0, s);
                    p1 += __shfl_xor_sync(0xFFFFFFFFu, p1, s);
                    p2 += __shfl_xor_sync(0xFFFFFFFFu, p2, s);
                    p3 += __shfl_xor_sync(0xFFFFFFFFu, p3, s);
                    q0 += __shfl_xor_sync(0xFFFFFFFFu, q0, s);
                    q1 += __shfl_xor_sync(0xFFFFFFFFu, q1, s);
                    q2 += __shfl_xor_sync(0xFFFFFFFFu, q2, s);
                    q3 += __shfl_xor_sync(0xFFFFFFFFu, q3, s);
                }
                if ((lane & 3) == 0) {
                    int rr = mt * 16 + (lane >> 2);
                    sYp[w][rr][0] = p0; sYp[w][rr][1] = p1;
                    sYp[w][rr][2] = p2; sYp[w][rr][3] = p3;
                    sYp[w][rr + 8][0] = q0; sYp[w][rr + 8][1] = q1;
                    sYp[w][rr + 8][2] = q2; sYp[w][rr + 8][3] = q3;
                }
            }
        }
        __syncthreads();
        if (do_proj && t < 128) {
            int row = t >> 2, o = t & 3;
            float s = sYp[0][row][o] + sYp[1][row][o] + sYp[2][row][o] + sYp[3][row][o]
                    + sYp[4][row][o] + sYp[5][row][o] + sYp[6][row][o] + sYp[7][row][o];
            int node = base + row;
            if (o < 2) {
                g_y[node * 2 + o] = s;
            } else {
                int gb = load_idx(batch, node);
                atomicAdd(&pb[gb * 2 + (o - 2)], s);
            }
        }
    }
    if (do_proj) {
        __syncthreads();
        if (t < N_GRAPHS * 2 && pb[t] != 0.f) atomicAdd(&g_pool[t], pb[t]);
    }
}

// ---- K8: gather 2-dim y over edges + pool + last-block output + cleanup --
__global__ void k_gather2(const void* __restrict__ batch,
                          const float* __restrict__ b_out,
                          float* __restrict__ out) {
    __shared__ float sp[N_GRAPHS * 2];
    __shared__ int s_last;
    for (int i = threadIdx.x; i < N_GRAPHS * 2; i += blockDim.x) sp[i] = 0.f;
    __syncthreads();
    int n = blockIdx.x * blockDim.x + threadIdx.x;
    if (n < N_NODES) {
        int deg = g_deg[n];
        int de = min(deg, SRC_CAP);
        g_deg[n] = 0;   // restore zero-invariant (last reader)
        const int* spn = g_srcs + n * SRC_CAP;
        const float2* y2 = (const float2*)g_y;
        float a0 = 0.f, a1 = 0.f, b0 = 0.f, b1 = 0.f;
        int e = 0;
        for (; e + 4 <= de; e += 4) {
            float2 v0 = y2[spn[e]];
            float2 v1 = y2[spn[e + 1]];
            float2 v2 = y2[spn[e + 2]];
            float2 v3 = y2[spn[e + 3]];
            a0 += v0.x + v1.x; b0 += v2.x + v3.x;
            a1 += v0.y + v1.y; b1 += v2.y + v3.y;
        }
        for (; e < de; e++) {
            float2 v = y2[spn[e]];
            a0 += v.x; a1 += v.y;
        }
        float iv = deg > 0 ? 1.0f / (float)deg : 0.f;
        int g = load_idx(batch, n);
        atomicAdd(&sp[g * 2 + 0], (a0 + b0) * iv);
        atomicAdd(&sp[g * 2 + 1], (a1 + b1) * iv);
    }
    __syncthreads();
    for (int i = threadIdx.x; i < N_GRAPHS * 2; i += blockDim.x)
        if (sp[i] != 0.f) atomicAdd(&g_pool[i], sp[i]);

    __threadfence();
    __syncthreads();
    if (threadIdx.x == 0)
        s_last = (atomicAdd(&g_done, 1) == (int)gridDim.x - 1) ? 1 : 0;
    __syncthreads();
    if (s_last) {
        int i = threadIdx.x;
        float p = 0.f; int cnum = 0;
        if (i < N_GRAPHS * 2) {
            cnum = g_gcnt[i >> 1];
            p = g_pool[i];
            out[i] = (cnum > 0 ? p / (float)cnum : 0.f) + b_out[i & 1];
        }
        __syncthreads();
        if (i < N_GRAPHS * 2) {
            g_pool[i] = 0.f;
            if ((i & 1) == 0) g_gcnt[i >> 1] = 0;
        }
        if (i == 0) g_done = 0;
    }
}

// ---------------- launch ---------------------------------------------------
extern "C" void kernel_launch(void* const* d_in, const int* in_sizes, int n_in,
                              void* d_out, int out_size) {
    const float* x      = (const float*)d_in[0];
    const void*  edges  = d_in[1];
    const void*  batch  = d_in[2];
    const float* Wl     = (const float*)d_in[3];
    const float* Wr     = (const float*)d_in[4];
    const float* b      = (const float*)d_in[5];
    const float* Wl_out = (const float*)d_in[6];
    const float* Wr_out = (const float*)d_in[7];
    const float* b_out  = (const float*)d_in[8];
    float* out = (float*)d_out;
    int E = in_sizes[1] / 2;

    k_pro<<<(N_NODES * D / 4 + 255) / 256, 256>>>(edges, x, Wl, Wr, batch, E);

    k_aggregate<<<N_NODES / 8, 256>>>(0);
    k_linear_hmma<<<500, 256>>>(0, 1, 0, b, 0, Wl_out, Wr_out, batch);
    k_aggregate<<<N_NODES / 8, 256>>>(1);
    k_linear_hmma<<<500, 256>>>(1, 2, 1, b + 64, 0, Wl_out, Wr_out, batch);
    k_aggregate<<<N_NODES / 8, 256>>>(2);
    k_linear_hmma<<<500, 256>>>(2, 1, 2, b + 128, 1, Wl_out, Wr_out, batch);

    k_gather2<<<(N_NODES + 255) / 256, 256>>>(batch, b_out, out);
}